// round 2
// baseline (speedup 1.0000x reference)
#include <cuda_runtime.h>
#include <math.h>

// ---------------- problem constants ----------------
#define Bb 2
#define Nn 16384
#define Ee 131072
#define Cc 128
#define Kk 64

// ---------------- scratch (device globals; allocation-free) ----------------
__device__ float g_bC [Bb*Nn*Kk];   // cos bases (b,n,k), mask applied
__device__ float g_bS [Bb*Nn*Kk];   // sin bases
__device__ float g_wbc[Bb*Nn*Kk];   // weighted cos bases
__device__ float g_wbs[Bb*Nn*Kk];   // weighted sin bases
__device__ float g_w0 [Bb*Nn];      // mask*node_weight

__device__ float g_h  [Bb*Cc*Nn];   // current h (b,c,n)
__device__ float g_hn [Bb*Cc*Nn];   // hnew pre-activation (b,c,n)
__device__ float g_m  [Bb*Cc*Nn];   // MLP intermediate / fc1 output
__device__ float g_f  [Bb*Nn*Cc];   // f transposed (b,n,c) for edge gather
__device__ float g_x3 [Bb*Cc*Nn];   // scatter target (b,c,n)

__device__ float g_xc [Bb*Cc*Kk];
__device__ float g_xs [Bb*Cc*Kk];   // stores reference xs (minus applied)
__device__ float g_x0 [Bb*Cc];
__device__ float g_fch[Bb*Cc*Kk];
__device__ float g_fsh[Bb*Cc*Kk];
__device__ float g_f0h[Bb*Cc];
__device__ float g_ker[Bb*Ee];

__device__ __forceinline__ float gelu_f(float x){
    return 0.5f * x * (1.0f + erff(x * 0.7071067811865475f));
}

__device__ __forceinline__ float* bufsel(int s){
    if (s == 0) return g_h;
    if (s == 1) return g_hn;
    if (s == 2) return g_m;
    return g_f;
}

// ---------------- K1: Fourier bases ----------------
__global__ void bases_kernel(const float* __restrict__ nodes,
                             const float* __restrict__ modes,
                             const float* __restrict__ mask,
                             const float* __restrict__ nw){
    int idx = blockIdx.x * blockDim.x + threadIdx.x;
    if (idx >= Bb*Nn*Kk) return;
    int k  = idx & (Kk-1);
    int ng = idx >> 6;                       // b*N + n
    float nx = nodes[ng*2+0], ny = nodes[ng*2+1];
    float tt = nx*modes[k*2+0] + ny*modes[k*2+1];
    float s, c;
    sincosf(tt, &s, &c);
    float mk = mask[ng], w = nw[ng];
    c *= mk; s *= mk;
    g_bC[idx]  = c;   g_bS[idx]  = s;
    g_wbc[idx] = c*w; g_wbs[idx] = s*w;
    if (k == 0) g_w0[ng] = mk * w;
}

// ---------------- K2: fc0 lift ----------------
__global__ void fc0_kernel(const float* __restrict__ x,
                           const float* __restrict__ w,
                           const float* __restrict__ bia){
    int idx = blockIdx.x * blockDim.x + threadIdx.x;
    if (idx >= Bb*Cc*Nn) return;
    int n = idx & (Nn-1);
    int c = (idx >> 14) & (Cc-1);
    int b = idx >> 21;
    const float* xr = x + ((size_t)(b*Nn + n))*3;
    g_h[idx] = xr[0]*w[c] + xr[1]*w[Cc+c] + xr[2]*w[2*Cc+c] + bia[c];
}

// ---------------- zero helpers ----------------
__global__ void zero_spec_kernel(){
    int idx = blockIdx.x * blockDim.x + threadIdx.x;
    if (idx < Bb*Cc*Kk){ g_xc[idx] = 0.f; g_xs[idx] = 0.f; }
    if (idx < Bb*Cc)     g_x0[idx] = 0.f;
}
__global__ void zero_x3_kernel(){
    int idx = blockIdx.x * blockDim.x + threadIdx.x;
    if (idx < Bb*Cc*Nn) g_x3[idx] = 0.f;
}

// ---------------- K3: projection h @ wb{c,s,0}  (atomics into tiny output) ----
// grid (Nn/128, 1, Bb), 256 threads, dynamic smem
#define PROJ_SMEM_FLOATS (8192+8192+128+512+2304+16)
__global__ void __launch_bounds__(256) proj_kernel(){
    extern __shared__ float sm[];
    float* wc   = sm;             // [128n][64k]
    float* ws   = sm + 8192;
    float* w0s  = sm + 16384;     // [128]
    float* hs   = sm + 16512;     // [4c][128n]
    float* red  = sm + 17024;     // [256][stride 9]
    float* red0 = sm + 19328;     // [16]
    int b  = blockIdx.z;
    int n0 = blockIdx.x * 128;
    int t  = threadIdx.x;

    size_t gbase = ((size_t)(b*Nn + n0)) * Kk;
    for (int id = t*4; id < 8192; id += 1024){
        *(float4*)&wc[id] = *(const float4*)(g_wbc + gbase + id);
        *(float4*)&ws[id] = *(const float4*)(g_wbs + gbase + id);
    }
    if (t < 128) w0s[t] = g_w0[b*Nn + n0 + t];
    __syncthreads();

    int k = t & 63, g = t >> 6;
    for (int c0 = 0; c0 < Cc; c0 += 4){
        // load 4 h rows
        {
            int id = t*2;
            int ci = id >> 7, nl = id & 127;
            const float* hp = g_h + ((size_t)(b*Cc + c0 + ci))*Nn + n0 + nl;
            hs[id]   = hp[0];
            hs[id+1] = hp[1];
        }
        __syncthreads();
        float aC[4] = {0,0,0,0}, aS[4] = {0,0,0,0}, a0[4] = {0,0,0,0};
        #pragma unroll 4
        for (int j = 0; j < 32; j++){
            int nl = g*32 + j;
            float wcv = wc[nl*64 + k];
            float wsv = ws[nl*64 + k];
            #pragma unroll
            for (int ci = 0; ci < 4; ci++){
                float hv = hs[ci*128 + nl];
                aC[ci] = fmaf(hv, wcv, aC[ci]);
                aS[ci] = fmaf(hv, wsv, aS[ci]);
            }
            if (k == 0){
                float w0v = w0s[nl];
                #pragma unroll
                for (int ci = 0; ci < 4; ci++) a0[ci] = fmaf(hs[ci*128+nl], w0v, a0[ci]);
            }
        }
        #pragma unroll
        for (int ci = 0; ci < 4; ci++){
            red[t*9 + ci*2 + 0] = aC[ci];
            red[t*9 + ci*2 + 1] = aS[ci];
        }
        if (k == 0){
            #pragma unroll
            for (int ci = 0; ci < 4; ci++) red0[g*4 + ci] = a0[ci];
        }
        __syncthreads();
        if (t < 64){
            #pragma unroll
            for (int ci = 0; ci < 4; ci++){
                float sC = red[t*9+ci*2]   + red[(t+64)*9+ci*2]
                         + red[(t+128)*9+ci*2] + red[(t+192)*9+ci*2];
                float sS = red[t*9+ci*2+1] + red[(t+64)*9+ci*2+1]
                         + red[(t+128)*9+ci*2+1] + red[(t+192)*9+ci*2+1];
                atomicAdd(&g_xc[(b*Cc + c0 + ci)*Kk + t],  sC);
                atomicAdd(&g_xs[(b*Cc + c0 + ci)*Kk + t], -sS);  // xs = -h@wbs
            }
        }
        if (t < 4){
            float s0 = red0[t] + red0[4+t] + red0[8+t] + red0[12+t];
            atomicAdd(&g_x0[b*Cc + c0 + t], s0);
        }
        __syncthreads();
    }
}

// ---------------- K4: spectral mix (per-k complex C x C) ----------------
__global__ void specmix_kernel(const float* __restrict__ wcp,
                               const float* __restrict__ wsp){
    int idx = blockIdx.x * blockDim.x + threadIdx.x;
    if (idx >= Bb*Cc*Kk) return;
    int k = idx & 63;
    int o = (idx >> 6) & 127;
    int b = idx >> 13;
    float fc = 0.f, fs = 0.f;
    for (int i = 0; i < Cc; i++){
        float xc = g_xc[(b*Cc + i)*Kk + k];
        float xs = g_xs[(b*Cc + i)*Kk + k];
        float a  = wcp[((size_t)(i*Cc + o))*Kk + k];
        float bv = wsp[((size_t)(i*Cc + o))*Kk + k];
        fc += xc*a - xs*bv;
        fs += xs*a + xc*bv;
    }
    g_fch[idx] = fc;
    g_fsh[idx] = fs;
}

__global__ void specmix0_kernel(const float* __restrict__ w0p){
    int t = threadIdx.x;              // 256 = Bb*Cc
    int b = t >> 7, o = t & 127;
    float acc = 0.f;
    for (int i = 0; i < Cc; i++)
        acc += g_x0[b*Cc + i] * w0p[(size_t)i*Cc + o];
    g_f0h[t] = acc;
}

// ---------------- generic pointwise GEMM: Y = act(W . X + bias) ----------------
// X,Y: (b,c,n) layouts, 128x128 weights; grid (Nn/128,1,Bb)
template<bool TRANSW, bool ACT_GELU, bool STORE_T>
__global__ void __launch_bounds__(256) gemm128_kernel(const float* __restrict__ W,
                                                      const float* __restrict__ bias,
                                                      int xsel, int ysel){
    __shared__ float As[16][128];
    __shared__ float Bs[16][128];
    const float* X = bufsel(xsel);
    float*       Y = bufsel(ysel);
    int b  = blockIdx.z;
    int n0 = blockIdx.x * 128;
    const float* Xb = X + (size_t)b*Cc*Nn;
    int t  = threadIdx.x;
    int tx = t & 15, ty = t >> 4;
    float acc[8][8];
    #pragma unroll
    for (int i = 0; i < 8; i++)
        #pragma unroll
        for (int j = 0; j < 8; j++) acc[i][j] = 0.f;

    for (int k0 = 0; k0 < Cc; k0 += 16){
        int id = t*8;
        int kk = id >> 7, oo = id & 127;
        if (TRANSW){
            float4 a0 = *(const float4*)(W + (size_t)(k0+kk)*Cc + oo);
            float4 a1 = *(const float4*)(W + (size_t)(k0+kk)*Cc + oo + 4);
            *(float4*)&As[kk][oo]   = a0;
            *(float4*)&As[kk][oo+4] = a1;
        } else {
            #pragma unroll
            for (int j = 0; j < 8; j++) As[kk][oo+j] = W[(size_t)(oo+j)*Cc + k0 + kk];
        }
        float4 b0 = *(const float4*)(Xb + (size_t)(k0+kk)*Nn + n0 + oo);
        float4 b1 = *(const float4*)(Xb + (size_t)(k0+kk)*Nn + n0 + oo + 4);
        *(float4*)&Bs[kk][oo]   = b0;
        *(float4*)&Bs[kk][oo+4] = b1;
        __syncthreads();
        #pragma unroll
        for (int kq = 0; kq < 16; kq++){
            float a[8], bb[8];
            *(float4*)(a)    = *(const float4*)&As[kq][ty*8];
            *(float4*)(a+4)  = *(const float4*)&As[kq][ty*8+4];
            *(float4*)(bb)   = *(const float4*)&Bs[kq][tx*8];
            *(float4*)(bb+4) = *(const float4*)&Bs[kq][tx*8+4];
            #pragma unroll
            for (int i = 0; i < 8; i++)
                #pragma unroll
                for (int j = 0; j < 8; j++)
                    acc[i][j] = fmaf(a[i], bb[j], acc[i][j]);
        }
        __syncthreads();
    }
    float bi[8];
    #pragma unroll
    for (int i = 0; i < 8; i++) bi[i] = bias[ty*8+i];
    if (!STORE_T){
        #pragma unroll
        for (int i = 0; i < 8; i++){
            int o = ty*8 + i;
            float v[8];
            #pragma unroll
            for (int j = 0; j < 8; j++){
                float u = acc[i][j] + bi[i];
                v[j] = ACT_GELU ? gelu_f(u) : u;
            }
            float* yp = Y + (size_t)(b*Cc + o)*Nn + n0 + tx*8;
            *(float4*)yp     = *(float4*)v;
            *(float4*)(yp+4) = *(float4*)(v+4);
        }
    } else {
        #pragma unroll
        for (int j = 0; j < 8; j++){
            int n = n0 + tx*8 + j;
            float v[8];
            #pragma unroll
            for (int i = 0; i < 8; i++){
                float u = acc[i][j] + bi[i];
                v[i] = ACT_GELU ? gelu_f(u) : u;
            }
            float* yp = Y + ((size_t)b*Nn + n)*Cc + ty*8;
            *(float4*)yp     = *(float4*)v;
            *(float4*)(yp+4) = *(float4*)(v+4);
        }
    }
}

// ---------------- K5: spectral reconstruction (accumulate into g_hn) --------
// hnew += 2*fc_h.bC^T - 2*fs_h.bS^T + f0_h*mask ; grid (Nn/128,1,Bb)
#define RECON_SMEM_FLOATS (4*8192)
__global__ void __launch_bounds__(256) recon_kernel(const float* __restrict__ mask){
    extern __shared__ float sm[];
    float* AsC = sm;             // [64k][128c] = 2*fc_h
    float* AsS = sm + 8192;      // -2*fs_h
    float* BsC = sm + 16384;     // [64k][128n]
    float* BsS = sm + 24576;
    int b  = blockIdx.z;
    int n0 = blockIdx.x * 128;
    int t  = threadIdx.x;

    for (int id = t*4; id < 8192; id += 1024){
        int c = id >> 6, k = id & 63;
        float4 v = *(const float4*)(g_fch + (size_t)(b*Cc + c)*Kk + k);
        AsC[(k+0)*128+c] =  2.f*v.x; AsC[(k+1)*128+c] =  2.f*v.y;
        AsC[(k+2)*128+c] =  2.f*v.z; AsC[(k+3)*128+c] =  2.f*v.w;
        float4 w = *(const float4*)(g_fsh + (size_t)(b*Cc + c)*Kk + k);
        AsS[(k+0)*128+c] = -2.f*w.x; AsS[(k+1)*128+c] = -2.f*w.y;
        AsS[(k+2)*128+c] = -2.f*w.z; AsS[(k+3)*128+c] = -2.f*w.w;
    }
    for (int id = t*4; id < 8192; id += 1024){
        int nl = id >> 6, k = id & 63;
        float4 v = *(const float4*)(g_bC + ((size_t)(b*Nn + n0 + nl))*Kk + k);
        BsC[(k+0)*128+nl] = v.x; BsC[(k+1)*128+nl] = v.y;
        BsC[(k+2)*128+nl] = v.z; BsC[(k+3)*128+nl] = v.w;
        float4 w = *(const float4*)(g_bS + ((size_t)(b*Nn + n0 + nl))*Kk + k);
        BsS[(k+0)*128+nl] = w.x; BsS[(k+1)*128+nl] = w.y;
        BsS[(k+2)*128+nl] = w.z; BsS[(k+3)*128+nl] = w.w;
    }
    __syncthreads();

    int tx = t & 15, ty = t >> 4;
    float acc[8][8];
    #pragma unroll
    for (int i = 0; i < 8; i++)
        #pragma unroll
        for (int j = 0; j < 8; j++) acc[i][j] = 0.f;

    #pragma unroll 4
    for (int k = 0; k < Kk; k++){
        float aC[8], aS[8], bC8[8], bS8[8];
        *(float4*)(aC)    = *(const float4*)&AsC[k*128 + ty*8];
        *(float4*)(aC+4)  = *(const float4*)&AsC[k*128 + ty*8 + 4];
        *(float4*)(aS)    = *(const float4*)&AsS[k*128 + ty*8];
        *(float4*)(aS+4)  = *(const float4*)&AsS[k*128 + ty*8 + 4];
        *(float4*)(bC8)   = *(const float4*)&BsC[k*128 + tx*8];
        *(float4*)(bC8+4) = *(const float4*)&BsC[k*128 + tx*8 + 4];
        *(float4*)(bS8)   = *(const float4*)&BsS[k*128 + tx*8];
        *(float4*)(bS8+4) = *(const float4*)&BsS[k*128 + tx*8 + 4];
        #pragma unroll
        for (int i = 0; i < 8; i++)
            #pragma unroll
            for (int j = 0; j < 8; j++){
                acc[i][j] = fmaf(aC[i], bC8[j], acc[i][j]);
                acc[i][j] = fmaf(aS[i], bS8[j], acc[i][j]);
            }
    }
    float mv[8];
    #pragma unroll
    for (int j = 0; j < 8; j++) mv[j] = mask[(size_t)b*Nn + n0 + tx*8 + j];
    #pragma unroll
    for (int i = 0; i < 8; i++){
        int o = ty*8 + i;
        float f0 = g_f0h[b*Cc + o];
        float* yp = g_hn + (size_t)(b*Cc + o)*Nn + n0 + tx*8;
        float4 y0 = *(float4*)yp, y1 = *(float4*)(yp+4);
        y0.x += acc[i][0] + f0*mv[0]; y0.y += acc[i][1] + f0*mv[1];
        y0.z += acc[i][2] + f0*mv[2]; y0.w += acc[i][3] + f0*mv[3];
        y1.x += acc[i][4] + f0*mv[4]; y1.y += acc[i][5] + f0*mv[5];
        y1.z += acc[i][6] + f0*mv[6]; y1.w += acc[i][7] + f0*mv[7];
        *(float4*)yp     = y0;
        *(float4*)(yp+4) = y1;
    }
}

// ---------------- edge kernels ----------------
__global__ void ker_kernel(const int* __restrict__ edges,
                           const float* __restrict__ nodes,
                           const float* __restrict__ isw,
                           const float* __restrict__ isb,
                           const float* __restrict__ gc, int l){
    int gid = blockIdx.x * blockDim.x + threadIdx.x;
    if (gid >= Bb*Ee) return;
    int b = (gid >= Ee) ? 1 : 0;
    int src = edges[(size_t)gid*2 + 0];
    int tgt = edges[(size_t)gid*2 + 1];
    int base = b*Nn;
    float dx = nodes[(size_t)(base+src)*2+0] - nodes[(size_t)(base+tgt)*2+0];
    float dy = nodes[(size_t)(base+src)*2+1] - nodes[(size_t)(base+tgt)*2+1];
    float s0 = dx*isw[0] + dy*isw[1] + isb[0];
    float s1 = dx*isw[2] + dy*isw[3] + isb[1];
    g_ker[gid] = gc[l] * expf(dx*s0 + dy*s1);
}

// warp per edge: gather f[src] (contiguous), scatter-add ker*f into x3(b,c,n)
__global__ void scatter_kernel(const int* __restrict__ edges){
    int gid  = (blockIdx.x * blockDim.x + threadIdx.x) >> 5;
    int lane = threadIdx.x & 31;
    if (gid >= Bb*Ee) return;
    int b   = (gid >= Ee) ? 1 : 0;
    int src = edges[(size_t)gid*2 + 0];
    int tgt = edges[(size_t)gid*2 + 1];
    float kv = g_ker[gid];
    float4 f4 = *(const float4*)(g_f + ((size_t)(b*Nn + src))*Cc + lane*4);
    float* xb = g_x3 + (size_t)b*Cc*Nn;
    atomicAdd(xb + (size_t)(lane*4+0)*Nn + tgt, f4.x*kv);
    atomicAdd(xb + (size_t)(lane*4+1)*Nn + tgt, f4.y*kv);
    atomicAdd(xb + (size_t)(lane*4+2)*Nn + tgt, f4.z*kv);
    atomicAdd(xb + (size_t)(lane*4+3)*Nn + tgt, f4.w*kv);
}

// h_next = gelu(hnew) + gelu(x3)   (writes back into g_h)
__global__ void combine_kernel(){
    int idx = blockIdx.x * blockDim.x + threadIdx.x;
    if (idx >= Bb*Cc*Nn) return;
    g_h[idx] = gelu_f(g_hn[idx]) + gelu_f(g_x3[idx]);
}

// ---------------- final projection fc2 ----------------
__global__ void fc2_kernel(const float* __restrict__ w2,
                           const float* __restrict__ b2,
                           float* __restrict__ out){
    int idx = blockIdx.x * blockDim.x + threadIdx.x;
    if (idx >= Bb*Nn) return;
    int b = idx >> 14, n = idx & (Nn-1);
    float acc = b2[0];
    for (int i = 0; i < Cc; i++)
        acc += g_m[((size_t)(b*Cc + i))*Nn + n] * w2[i];
    out[idx] = acc;
}

// ---------------- host orchestration ----------------
extern "C" void kernel_launch(void* const* d_in, const int* in_sizes, int n_in,
                              void* d_out, int out_size){
    const float* x            = (const float*)d_in[0];
    const float* node_mask    = (const float*)d_in[1];
    const float* nodes        = (const float*)d_in[2];
    const float* node_weights = (const float*)d_in[3];
    const int*   edges        = (const int*)  d_in[4];
    const float* modes        = (const float*)d_in[5];
    const float* fc0_w        = (const float*)d_in[6];
    const float* fc0_b        = (const float*)d_in[7];
    const float* sp_wc        = (const float*)d_in[8];
    const float* sp_ws        = (const float*)d_in[9];
    const float* sp_w0        = (const float*)d_in[10];
    const float* w_w          = (const float*)d_in[11];
    const float* w_b          = (const float*)d_in[12];
    const float* g_w1         = (const float*)d_in[13];
    const float* g_b1         = (const float*)d_in[14];
    const float* g_w2         = (const float*)d_in[15];
    const float* g_b2         = (const float*)d_in[16];
    const float* isigma_w     = (const float*)d_in[17];
    const float* isigma_b     = (const float*)d_in[18];
    const float* gC           = (const float*)d_in[19];
    const float* fc1_w        = (const float*)d_in[20];
    const float* fc1_b        = (const float*)d_in[21];
    const float* fc2_w        = (const float*)d_in[22];
    const float* fc2_b        = (const float*)d_in[23];
    float* out = (float*)d_out;

    cudaFuncSetAttribute(proj_kernel,  cudaFuncAttributeMaxDynamicSharedMemorySize,
                         PROJ_SMEM_FLOATS * 4);
    cudaFuncSetAttribute(recon_kernel, cudaFuncAttributeMaxDynamicSharedMemorySize,
                         RECON_SMEM_FLOATS * 4);

    dim3 gtile(Nn/128, 1, Bb);

    bases_kernel<<<(Bb*Nn*Kk + 255)/256, 256>>>(nodes, modes, node_mask, node_weights);
    fc0_kernel<<<(Bb*Cc*Nn + 255)/256, 256>>>(x, fc0_w, fc0_b);

    for (int l = 0; l < 4; l++){
        zero_spec_kernel<<<64, 256>>>();
        proj_kernel<<<gtile, 256, PROJ_SMEM_FLOATS * 4>>>();
        specmix_kernel<<<64, 256>>>(sp_wc + (size_t)l*Cc*Cc*Kk,
                                    sp_ws + (size_t)l*Cc*Cc*Kk);
        specmix0_kernel<<<1, 256>>>(sp_w0 + (size_t)l*Cc*Cc);
        // x2 = w_w . h + w_b  -> g_hn
        gemm128_kernel<false,false,false><<<gtile, 256>>>(w_w + (size_t)l*Cc*Cc,
                                                          w_b + (size_t)l*Cc, 0, 1);
        // g_hn += spectral reconstruction
        recon_kernel<<<gtile, 256, RECON_SMEM_FLOATS * 4>>>(node_mask);

        if (l < 3){
            // m = gelu(g_w1 . h + g_b1) -> g_m
            gemm128_kernel<false,true,false><<<gtile, 256>>>(g_w1 + (size_t)l*Cc*Cc,
                                                             g_b1 + (size_t)l*Cc, 0, 2);
            // f = g_w2 . m + g_b2  -> g_f transposed (b,n,c)
            gemm128_kernel<false,false,true><<<gtile, 256>>>(g_w2 + (size_t)l*Cc*Cc,
                                                             g_b2 + (size_t)l*Cc, 2, 3);
            zero_x3_kernel<<<(Bb*Cc*Nn + 255)/256, 256>>>();
            ker_kernel<<<(Bb*Ee + 255)/256, 256>>>(edges, nodes,
                                                   isigma_w + l*4, isigma_b + l*2, gC, l);
            scatter_kernel<<<(Bb*Ee)/8, 256>>>(edges);
            combine_kernel<<<(Bb*Cc*Nn + 255)/256, 256>>>();
        }
    }
    // fc1: gelu(h . fc1_w + fc1_b) ; fc1_w is (i,o) -> TRANSW. input g_hn, out g_m
    gemm128_kernel<true,true,false><<<gtile, 256>>>(fc1_w, fc1_b, 1, 2);
    fc2_kernel<<<(Bb*Nn + 255)/256, 256>>>(fc2_w, fc2_b, out);
}

// round 5
// speedup vs baseline: 1.1221x; 1.1221x over previous
#include <cuda_runtime.h>
#include <math.h>

// ---------------- problem constants ----------------
#define Bb 2
#define Nn 16384
#define Ee 131072
#define Cc 128
#define Kk 64

// ---------------- scratch (device globals; allocation-free) ----------------
__device__ float g_bC [Bb*Nn*Kk];   // cos bases (b,n,k), mask applied
__device__ float g_bS [Bb*Nn*Kk];   // sin bases
__device__ float g_wbc[Bb*Nn*Kk];   // weighted cos bases
__device__ float g_wbs[Bb*Nn*Kk];   // weighted sin bases
__device__ float g_w0 [Bb*Nn];      // mask*node_weight

__device__ float g_h  [Bb*Cc*Nn];   // current h (b,c,n)
__device__ float g_hn [Bb*Cc*Nn];   // hnew pre-activation (b,c,n)
__device__ float g_f  [Bb*Nn*Cc];   // f transposed (b,n,c) for edge gather
__device__ float g_x3 [Bb*Cc*Nn];   // scatter target (b,c,n)

__device__ float g_xc [Bb*Cc*Kk];
__device__ float g_xs [Bb*Cc*Kk];   // reference xs (minus applied at write)
__device__ float g_x0 [Bb*Cc];
__device__ float g_fch[Bb*Cc*Kk];
__device__ float g_fsh[Bb*Cc*Kk];
__device__ float g_f0h[Bb*Cc];
__device__ float g_ker[Bb*Ee];

__device__ __forceinline__ float gelu_f(float x){
    return 0.5f * x * (1.0f + erff(x * 0.7071067811865475f));
}

// ---------------- K1: Fourier bases ----------------
__global__ void bases_kernel(const float* __restrict__ nodes,
                             const float* __restrict__ modes,
                             const float* __restrict__ mask,
                             const float* __restrict__ nw){
    int idx = blockIdx.x * blockDim.x + threadIdx.x;
    if (idx >= Bb*Nn*Kk) return;
    int k  = idx & (Kk-1);
    int ng = idx >> 6;                       // b*N + n
    float nx = nodes[ng*2+0], ny = nodes[ng*2+1];
    float tt = nx*modes[k*2+0] + ny*modes[k*2+1];
    float s, c;
    __sincosf(tt, &s, &c);
    float mk = mask[ng], w = nw[ng];
    c *= mk; s *= mk;
    g_bC[idx]  = c;   g_bS[idx]  = s;
    g_wbc[idx] = c*w; g_wbs[idx] = s*w;
    if (k == 0) g_w0[ng] = mk * w;
}

// ---------------- K2: fc0 lift ----------------
__global__ void fc0_kernel(const float* __restrict__ x,
                           const float* __restrict__ w,
                           const float* __restrict__ bia){
    int idx = blockIdx.x * blockDim.x + threadIdx.x;
    if (idx >= Bb*Cc*Nn) return;
    int n = idx & (Nn-1);
    int c = (idx >> 14) & (Cc-1);
    int b = idx >> 21;
    const float* xr = x + ((size_t)(b*Nn + n))*3;
    g_h[idx] = xr[0]*w[c] + xr[1]*w[Cc+c] + xr[2]*w[2*Cc+c] + bia[c];
}

// ---------------- zero helpers ----------------
__global__ void zero_spec_kernel(){
    int idx = blockIdx.x * blockDim.x + threadIdx.x;
    if (idx < Bb*Cc*Kk){ g_xc[idx] = 0.f; g_xs[idx] = 0.f; }
    if (idx < Bb*Cc)     g_x0[idx] = 0.f;
}
__global__ void zero_x3_kernel(){
    int idx = blockIdx.x * blockDim.x + threadIdx.x;
    if (idx < Bb*Cc*Nn) g_x3[idx] = 0.f;
}

// ---------------- K3: projection (split-K register-tile GEMM) ----------------
// xc/xs (128c x 64k per batch) held in registers per block; stream n.
// grid (Nn/256, 1, Bb), 256 threads
#define PROJ_NT 256
#define PROJ_CH 32
__global__ void __launch_bounds__(256) proj2_kernel(){
    __shared__ float hs[128*33];                 // h tile [c][32n] pad 33
    __shared__ float wcs[PROJ_CH*64];            // wbc  [n][64k]
    __shared__ float wss[PROJ_CH*64];            // wbs
    __shared__ float w0s[PROJ_CH];
    int b  = blockIdx.z;
    int n0 = blockIdx.x * PROJ_NT;
    int t  = threadIdx.x;
    int tx = t & 15, ty = t >> 4;                // tx -> 4 k's, ty -> 8 c's
    float accC[8][4], accS[8][4], acc0[8];
    #pragma unroll
    for (int i = 0; i < 8; i++){
        acc0[i] = 0.f;
        #pragma unroll
        for (int j = 0; j < 4; j++){ accC[i][j] = 0.f; accS[i][j] = 0.f; }
    }

    for (int ch = 0; ch < PROJ_NT/PROJ_CH; ch++){
        int nb = n0 + ch*PROJ_CH;
        #pragma unroll
        for (int p = 0; p < 4; p++){
            int idx = p*256 + t;                 // 1024 float4 = 128row x 8
            int row = idx >> 3, c4 = idx & 7;
            float4 v = *(const float4*)(g_h + (size_t)(b*Cc + row)*Nn + nb + c4*4);
            hs[row*33 + c4*4+0] = v.x; hs[row*33 + c4*4+1] = v.y;
            hs[row*33 + c4*4+2] = v.z; hs[row*33 + c4*4+3] = v.w;
        }
        #pragma unroll
        for (int p = 0; p < 2; p++){
            int idx = p*256 + t;                 // 512 float4 = 32row x 16
            int row = idx >> 4, k4 = idx & 15;
            *(float4*)&wcs[row*64 + k4*4] =
                *(const float4*)(g_wbc + ((size_t)(b*Nn + nb + row))*Kk + k4*4);
            *(float4*)&wss[row*64 + k4*4] =
                *(const float4*)(g_wbs + ((size_t)(b*Nn + nb + row))*Kk + k4*4);
        }
        if (t < PROJ_CH) w0s[t] = g_w0[b*Nn + nb + t];
        __syncthreads();

        #pragma unroll 4
        for (int nl = 0; nl < PROJ_CH; nl++){
            float4 wcv = *(float4*)&wcs[nl*64 + tx*4];
            float4 wsv = *(float4*)&wss[nl*64 + tx*4];
            float  w0v = w0s[nl];
            #pragma unroll
            for (int i = 0; i < 8; i++){
                float hv = hs[(ty*8+i)*33 + nl];
                accC[i][0] = fmaf(hv, wcv.x, accC[i][0]);
                accC[i][1] = fmaf(hv, wcv.y, accC[i][1]);
                accC[i][2] = fmaf(hv, wcv.z, accC[i][2]);
                accC[i][3] = fmaf(hv, wcv.w, accC[i][3]);
                accS[i][0] = fmaf(hv, wsv.x, accS[i][0]);
                accS[i][1] = fmaf(hv, wsv.y, accS[i][1]);
                accS[i][2] = fmaf(hv, wsv.z, accS[i][2]);
                accS[i][3] = fmaf(hv, wsv.w, accS[i][3]);
                acc0[i]    = fmaf(hv, w0v,   acc0[i]);
            }
        }
        __syncthreads();
    }
    #pragma unroll
    for (int i = 0; i < 8; i++){
        int c = ty*8 + i;
        #pragma unroll
        for (int j = 0; j < 4; j++){
            atomicAdd(&g_xc[(b*Cc + c)*Kk + tx*4 + j],  accC[i][j]);
            atomicAdd(&g_xs[(b*Cc + c)*Kk + tx*4 + j], -accS[i][j]);
        }
        if (tx == 0) atomicAdd(&g_x0[b*Cc + c], acc0[i]);
    }
}

// ---------------- K4: spectral mix (per-k complex C x C) ----------------
__global__ void specmix_kernel(const float* __restrict__ wcp,
                               const float* __restrict__ wsp){
    int idx = blockIdx.x * blockDim.x + threadIdx.x;
    if (idx >= Bb*Cc*Kk) return;
    int k = idx & 63;
    int o = (idx >> 6) & 127;
    int b = idx >> 13;
    float fc = 0.f, fs = 0.f;
    for (int i = 0; i < Cc; i++){
        float xc = g_xc[(b*Cc + i)*Kk + k];
        float xs = g_xs[(b*Cc + i)*Kk + k];
        float a  = wcp[((size_t)(i*Cc + o))*Kk + k];
        float bv = wsp[((size_t)(i*Cc + o))*Kk + k];
        fc += xc*a - xs*bv;
        fs += xs*a + xc*bv;
    }
    g_fch[idx] = fc;
    g_fsh[idx] = fs;
}

__global__ void specmix0_kernel(const float* __restrict__ w0p){
    int t = threadIdx.x;              // 256 = Bb*Cc
    int b = t >> 7, o = t & 127;
    float acc = 0.f;
    for (int i = 0; i < Cc; i++)
        acc += g_x0[b*Cc + i] * w0p[(size_t)i*Cc + o];
    g_f0h[t] = acc;
}

// ---------------- fused pointwise + spectral reconstruction ----------------
// g_hn = W.h + bias + 2*fc_h.bC^T - 2*fs_h.bS^T + f0*mask
// grid (Nn/128,1,Bb), 256 threads, 64KB dyn smem (2 x 8192 floats)
__global__ void __launch_bounds__(256) pwrecon_kernel(const float* __restrict__ W,
                                                      const float* __restrict__ bias,
                                                      const float* __restrict__ mask){
    extern __shared__ float sm[];
    float* As = sm;          // [64][128]
    float* Bs = sm + 8192;   // [64][128]
    int b  = blockIdx.z;
    int n0 = blockIdx.x * 128;
    int t  = threadIdx.x;
    int tx = t & 15, ty = t >> 4;
    float acc[8][8];
    #pragma unroll
    for (int i = 0; i < 8; i++)
        #pragma unroll
        for (int j = 0; j < 8; j++) acc[i][j] = 0.f;

    // ---- phase 1: W.h (k over 128 input channels, 2 chunks of 64) ----
    for (int k0 = 0; k0 < Cc; k0 += 64){
        #pragma unroll
        for (int p = 0; p < 8; p++){
            int idx = p*256 + t;                 // 2048 f4
            int row = idx >> 4, c4 = idx & 15;   // row=o, c4 -> i
            float4 v = *(const float4*)(W + (size_t)row*Cc + k0 + c4*4);
            As[(c4*4+0)*128 + row] = v.x; As[(c4*4+1)*128 + row] = v.y;
            As[(c4*4+2)*128 + row] = v.z; As[(c4*4+3)*128 + row] = v.w;
        }
        #pragma unroll
        for (int p = 0; p < 8; p++){
            int idx = p*256 + t;                 // 64 rows x 32 f4
            int row = idx >> 5, c4 = idx & 31;
            *(float4*)&Bs[row*128 + c4*4] =
                *(const float4*)(g_h + (size_t)(b*Cc + k0 + row)*Nn + n0 + c4*4);
        }
        __syncthreads();
        #pragma unroll 8
        for (int k = 0; k < 64; k++){
            float a[8], bb[8];
            *(float4*)(a)    = *(const float4*)&As[k*128 + ty*8];
            *(float4*)(a+4)  = *(const float4*)&As[k*128 + ty*8 + 4];
            *(float4*)(bb)   = *(const float4*)&Bs[k*128 + tx*8];
            *(float4*)(bb+4) = *(const float4*)&Bs[k*128 + tx*8 + 4];
            #pragma unroll
            for (int i = 0; i < 8; i++)
                #pragma unroll
                for (int j = 0; j < 8; j++)
                    acc[i][j] = fmaf(a[i], bb[j], acc[i][j]);
        }
        __syncthreads();
    }

    // ---- phase 2a: + 2*fc_h . bC^T ----
    #pragma unroll
    for (int p = 0; p < 8; p++){
        int idx = p*256 + t;                     // 128 c-rows x 16 f4
        int row = idx >> 4, k4 = idx & 15;
        float4 v = *(const float4*)(g_fch + (size_t)(b*Cc + row)*Kk + k4*4);
        As[(k4*4+0)*128 + row] = 2.f*v.x; As[(k4*4+1)*128 + row] = 2.f*v.y;
        As[(k4*4+2)*128 + row] = 2.f*v.z; As[(k4*4+3)*128 + row] = 2.f*v.w;
    }
    #pragma unroll
    for (int p = 0; p < 8; p++){
        int idx = p*256 + t;                     // 128 n-rows x 16 f4
        int nl = idx >> 4, k4 = idx & 15;
        float4 v = *(const float4*)(g_bC + ((size_t)(b*Nn + n0 + nl))*Kk + k4*4);
        Bs[(k4*4+0)*128 + nl] = v.x; Bs[(k4*4+1)*128 + nl] = v.y;
        Bs[(k4*4+2)*128 + nl] = v.z; Bs[(k4*4+3)*128 + nl] = v.w;
    }
    __syncthreads();
    #pragma unroll 8
    for (int k = 0; k < 64; k++){
        float a[8], bb[8];
        *(float4*)(a)    = *(const float4*)&As[k*128 + ty*8];
        *(float4*)(a+4)  = *(const float4*)&As[k*128 + ty*8 + 4];
        *(float4*)(bb)   = *(const float4*)&Bs[k*128 + tx*8];
        *(float4*)(bb+4) = *(const float4*)&Bs[k*128 + tx*8 + 4];
        #pragma unroll
        for (int i = 0; i < 8; i++)
            #pragma unroll
            for (int j = 0; j < 8; j++)
                acc[i][j] = fmaf(a[i], bb[j], acc[i][j]);
    }
    __syncthreads();

    // ---- phase 2b: - 2*fs_h . bS^T ----
    #pragma unroll
    for (int p = 0; p < 8; p++){
        int idx = p*256 + t;
        int row = idx >> 4, k4 = idx & 15;
        float4 v = *(const float4*)(g_fsh + (size_t)(b*Cc + row)*Kk + k4*4);
        As[(k4*4+0)*128 + row] = -2.f*v.x; As[(k4*4+1)*128 + row] = -2.f*v.y;
        As[(k4*4+2)*128 + row] = -2.f*v.z; As[(k4*4+3)*128 + row] = -2.f*v.w;
    }
    #pragma unroll
    for (int p = 0; p < 8; p++){
        int idx = p*256 + t;
        int nl = idx >> 4, k4 = idx & 15;
        float4 v = *(const float4*)(g_bS + ((size_t)(b*Nn + n0 + nl))*Kk + k4*4);
        Bs[(k4*4+0)*128 + nl] = v.x; Bs[(k4*4+1)*128 + nl] = v.y;
        Bs[(k4*4+2)*128 + nl] = v.z; Bs[(k4*4+3)*128 + nl] = v.w;
    }
    __syncthreads();
    #pragma unroll 8
    for (int k = 0; k < 64; k++){
        float a[8], bb[8];
        *(float4*)(a)    = *(const float4*)&As[k*128 + ty*8];
        *(float4*)(a+4)  = *(const float4*)&As[k*128 + ty*8 + 4];
        *(float4*)(bb)   = *(const float4*)&Bs[k*128 + tx*8];
        *(float4*)(bb+4) = *(const float4*)&Bs[k*128 + tx*8 + 4];
        #pragma unroll
        for (int i = 0; i < 8; i++)
            #pragma unroll
            for (int j = 0; j < 8; j++)
                acc[i][j] = fmaf(a[i], bb[j], acc[i][j]);
    }

    // ---- epilogue: + bias + f0*mask ----
    float mv[8];
    #pragma unroll
    for (int j = 0; j < 8; j++) mv[j] = mask[(size_t)b*Nn + n0 + tx*8 + j];
    #pragma unroll
    for (int i = 0; i < 8; i++){
        int o = ty*8 + i;
        float f0 = g_f0h[b*Cc + o];
        float bi = bias[o];
        float v[8];
        #pragma unroll
        for (int j = 0; j < 8; j++) v[j] = acc[i][j] + bi + f0*mv[j];
        float* yp = g_hn + (size_t)(b*Cc + o)*Nn + n0 + tx*8;
        *(float4*)yp     = *(float4*)v;
        *(float4*)(yp+4) = *(float4*)(v+4);
    }
}

// ---------------- fused MLP: f = W2.gelu(W1.h+b1)+b2 (stored (b,n,c)) -------
// grid (Nn/128,1,Bb), 256 threads, 128KB dyn smem
__global__ void __launch_bounds__(256) mlp_kernel(const float* __restrict__ W1,
                                                  const float* __restrict__ b1,
                                                  const float* __restrict__ W2,
                                                  const float* __restrict__ b2){
    extern __shared__ float sm[];
    float* As = sm;           // [64][128]
    float* Bs = sm + 8192;    // [64][128]
    float* Ms = sm + 16384;   // [128][128] intermediate m
    int b  = blockIdx.z;
    int n0 = blockIdx.x * 128;
    int t  = threadIdx.x;
    int tx = t & 15, ty = t >> 4;
    float acc[8][8];
    #pragma unroll
    for (int i = 0; i < 8; i++)
        #pragma unroll
        for (int j = 0; j < 8; j++) acc[i][j] = 0.f;

    // ---- phase 1: m = gelu(W1.h + b1) -> Ms ----
    for (int k0 = 0; k0 < Cc; k0 += 64){
        #pragma unroll
        for (int p = 0; p < 8; p++){
            int idx = p*256 + t;
            int row = idx >> 4, c4 = idx & 15;
            float4 v = *(const float4*)(W1 + (size_t)row*Cc + k0 + c4*4);
            As[(c4*4+0)*128 + row] = v.x; As[(c4*4+1)*128 + row] = v.y;
            As[(c4*4+2)*128 + row] = v.z; As[(c4*4+3)*128 + row] = v.w;
        }
        #pragma unroll
        for (int p = 0; p < 8; p++){
            int idx = p*256 + t;
            int row = idx >> 5, c4 = idx & 31;
            *(float4*)&Bs[row*128 + c4*4] =
                *(const float4*)(g_h + (size_t)(b*Cc + k0 + row)*Nn + n0 + c4*4);
        }
        __syncthreads();
        #pragma unroll 8
        for (int k = 0; k < 64; k++){
            float a[8], bb[8];
            *(float4*)(a)    = *(const float4*)&As[k*128 + ty*8];
            *(float4*)(a+4)  = *(const float4*)&As[k*128 + ty*8 + 4];
            *(float4*)(bb)   = *(const float4*)&Bs[k*128 + tx*8];
            *(float4*)(bb+4) = *(const float4*)&Bs[k*128 + tx*8 + 4];
            #pragma unroll
            for (int i = 0; i < 8; i++)
                #pragma unroll
                for (int j = 0; j < 8; j++)
                    acc[i][j] = fmaf(a[i], bb[j], acc[i][j]);
        }
        __syncthreads();
    }
    #pragma unroll
    for (int i = 0; i < 8; i++){
        int o = ty*8 + i;
        float bi = b1[o];
        float v[8];
        #pragma unroll
        for (int j = 0; j < 8; j++) v[j] = gelu_f(acc[i][j] + bi);
        *(float4*)&Ms[o*128 + tx*8]     = *(float4*)v;
        *(float4*)&Ms[o*128 + tx*8 + 4] = *(float4*)(v+4);
    }
    __syncthreads();

    // ---- phase 2: f = W2.m + b2 ----
    #pragma unroll
    for (int i = 0; i < 8; i++)
        #pragma unroll
        for (int j = 0; j < 8; j++) acc[i][j] = 0.f;
    for (int k0 = 0; k0 < Cc; k0 += 64){
        #pragma unroll
        for (int p = 0; p < 8; p++){
            int idx = p*256 + t;
            int row = idx >> 4, c4 = idx & 15;
            float4 v = *(const float4*)(W2 + (size_t)row*Cc + k0 + c4*4);
            As[(c4*4+0)*128 + row] = v.x; As[(c4*4+1)*128 + row] = v.y;
            As[(c4*4+2)*128 + row] = v.z; As[(c4*4+3)*128 + row] = v.w;
        }
        __syncthreads();
        const float* Bm = Ms + k0*128;
        #pragma unroll 8
        for (int k = 0; k < 64; k++){
            float a[8], bb[8];
            *(float4*)(a)    = *(const float4*)&As[k*128 + ty*8];
            *(float4*)(a+4)  = *(const float4*)&As[k*128 + ty*8 + 4];
            *(float4*)(bb)   = *(const float4*)&Bm[k*128 + tx*8];
            *(float4*)(bb+4) = *(const float4*)&Bm[k*128 + tx*8 + 4];
            #pragma unroll
            for (int i = 0; i < 8; i++)
                #pragma unroll
                for (int j = 0; j < 8; j++)
                    acc[i][j] = fmaf(a[i], bb[j], acc[i][j]);
        }
        __syncthreads();
    }
    // store transposed (b,n,c)
    float bi[8];
    #pragma unroll
    for (int i = 0; i < 8; i++) bi[i] = b2[ty*8+i];
    #pragma unroll
    for (int j = 0; j < 8; j++){
        int n = n0 + tx*8 + j;
        float v[8];
        #pragma unroll
        for (int i = 0; i < 8; i++) v[i] = acc[i][j] + bi[i];
        float* yp = g_f + ((size_t)b*Nn + n)*Cc + ty*8;
        *(float4*)yp     = *(float4*)v;
        *(float4*)(yp+4) = *(float4*)(v+4);
    }
}

// ---------------- fused fc1+fc2 head ----------------
// out[n] = gelu(hn^T.fc1_w + fc1_b) . fc2_w + fc2_b
// grid (Nn/128,1,Bb), 256 threads, 64KB dyn smem
__global__ void __launch_bounds__(256) fc_kernel(const float* __restrict__ W1,
                                                 const float* __restrict__ b1,
                                                 const float* __restrict__ w2,
                                                 const float* __restrict__ b2,
                                                 float* __restrict__ out){
    extern __shared__ float sm[];
    float* As = sm;          // [64][128]
    float* Bs = sm + 8192;
    int b  = blockIdx.z;
    int n0 = blockIdx.x * 128;
    int t  = threadIdx.x;
    int tx = t & 15, ty = t >> 4;
    float acc[8][8];
    #pragma unroll
    for (int i = 0; i < 8; i++)
        #pragma unroll
        for (int j = 0; j < 8; j++) acc[i][j] = 0.f;

    for (int k0 = 0; k0 < Cc; k0 += 64){
        // W1 is (i,o): rows i contiguous in o -> direct load
        #pragma unroll
        for (int p = 0; p < 8; p++){
            int idx = p*256 + t;                 // 64 rows x 32 f4
            int row = idx >> 5, c4 = idx & 31;
            *(float4*)&As[row*128 + c4*4] =
                *(const float4*)(W1 + (size_t)(k0 + row)*Cc + c4*4);
        }
        #pragma unroll
        for (int p = 0; p < 8; p++){
            int idx = p*256 + t;
            int row = idx >> 5, c4 = idx & 31;
            *(float4*)&Bs[row*128 + c4*4] =
                *(const float4*)(g_hn + (size_t)(b*Cc + k0 + row)*Nn + n0 + c4*4);
        }
        __syncthreads();
        #pragma unroll 8
        for (int k = 0; k < 64; k++){
            float a[8], bb[8];
            *(float4*)(a)    = *(const float4*)&As[k*128 + ty*8];
            *(float4*)(a+4)  = *(const float4*)&As[k*128 + ty*8 + 4];
            *(float4*)(bb)   = *(const float4*)&Bs[k*128 + tx*8];
            *(float4*)(bb+4) = *(const float4*)&Bs[k*128 + tx*8 + 4];
            #pragma unroll
            for (int i = 0; i < 8; i++)
                #pragma unroll
                for (int j = 0; j < 8; j++)
                    acc[i][j] = fmaf(a[i], bb[j], acc[i][j]);
        }
        __syncthreads();
    }
    // gelu + dot with fc2_w, partial over this thread's 8 o's
    float p8[8];
    #pragma unroll
    for (int j = 0; j < 8; j++) p8[j] = 0.f;
    #pragma unroll
    for (int i = 0; i < 8; i++){
        int o = ty*8 + i;
        float bi = b1[o], w2v = w2[o];
        #pragma unroll
        for (int j = 0; j < 8; j++)
            p8[j] = fmaf(gelu_f(acc[i][j] + bi), w2v, p8[j]);
    }
    // reduce over 16 ty groups via smem (reuse As)
    #pragma unroll
    for (int j = 0; j < 8; j++) As[ty*128 + tx*8 + j] = p8[j];
    __syncthreads();
    if (t < 128){
        float s = b2[0];
        #pragma unroll
        for (int g = 0; g < 16; g++) s += As[g*128 + t];
        out[(size_t)b*Nn + n0 + t] = s;
    }
}

// ---------------- edge kernels ----------------
__global__ void ker_kernel(const int* __restrict__ edges,
                           const float* __restrict__ nodes,
                           const float* __restrict__ isw,
                           const float* __restrict__ isb,
                           const float* __restrict__ gc, int l){
    int gid = blockIdx.x * blockDim.x + threadIdx.x;
    if (gid >= Bb*Ee) return;
    int b = (gid >= Ee) ? 1 : 0;
    int src = edges[(size_t)gid*2 + 0];
    int tgt = edges[(size_t)gid*2 + 1];
    int base = b*Nn;
    float dx = nodes[(size_t)(base+src)*2+0] - nodes[(size_t)(base+tgt)*2+0];
    float dy = nodes[(size_t)(base+src)*2+1] - nodes[(size_t)(base+tgt)*2+1];
    float s0 = dx*isw[0] + dy*isw[1] + isb[0];
    float s1 = dx*isw[2] + dy*isw[3] + isb[1];
    g_ker[gid] = gc[l] * expf(dx*s0 + dy*s1);
}

// warp per edge: gather f[src] (contiguous), scatter-add ker*f into x3(b,c,n)
__global__ void scatter_kernel(const int* __restrict__ edges){
    int gid  = (blockIdx.x * blockDim.x + threadIdx.x) >> 5;
    int lane = threadIdx.x & 31;
    if (gid >= Bb*Ee) return;
    int b   = (gid >= Ee) ? 1 : 0;
    int src = edges[(size_t)gid*2 + 0];
    int tgt = edges[(size_t)gid*2 + 1];
    float kv = g_ker[gid];
    float4 f4 = *(const float4*)(g_f + ((size_t)(b*Nn + src))*Cc + lane*4);
    float* xb = g_x3 + (size_t)b*Cc*Nn;
    atomicAdd(xb + (size_t)(lane*4+0)*Nn + tgt, f4.x*kv);
    atomicAdd(xb + (size_t)(lane*4+1)*Nn + tgt, f4.y*kv);
    atomicAdd(xb + (size_t)(lane*4+2)*Nn + tgt, f4.z*kv);
    atomicAdd(xb + (size_t)(lane*4+3)*Nn + tgt, f4.w*kv);
}

// h_next = gelu(hnew) + gelu(x3)
__global__ void combine_kernel(){
    int idx = blockIdx.x * blockDim.x + threadIdx.x;
    if (idx >= Bb*Cc*Nn) return;
    g_h[idx] = gelu_f(g_hn[idx]) + gelu_f(g_x3[idx]);
}

// ---------------- host orchestration ----------------
extern "C" void kernel_launch(void* const* d_in, const int* in_sizes, int n_in,
                              void* d_out, int out_size){
    const float* x            = (const float*)d_in[0];
    const float* node_mask    = (const float*)d_in[1];
    const float* nodes        = (const float*)d_in[2];
    const float* node_weights = (const float*)d_in[3];
    const int*   edges        = (const int*)  d_in[4];
    const float* modes        = (const float*)d_in[5];
    const float* fc0_w        = (const float*)d_in[6];
    const float* fc0_b        = (const float*)d_in[7];
    const float* sp_wc        = (const float*)d_in[8];
    const float* sp_ws        = (const float*)d_in[9];
    const float* sp_w0        = (const float*)d_in[10];
    const float* w_w          = (const float*)d_in[11];
    const float* w_b          = (const float*)d_in[12];
    const float* gw1          = (const float*)d_in[13];
    const float* gb1          = (const float*)d_in[14];
    const float* gw2          = (const float*)d_in[15];
    const float* gb2          = (const float*)d_in[16];
    const float* isigma_w     = (const float*)d_in[17];
    const float* isigma_b     = (const float*)d_in[18];
    const float* gC           = (const float*)d_in[19];
    const float* fc1_w        = (const float*)d_in[20];
    const float* fc1_b        = (const float*)d_in[21];
    const float* fc2_w        = (const float*)d_in[22];
    const float* fc2_b        = (const float*)d_in[23];
    float* out = (float*)d_out;

    cudaFuncSetAttribute(pwrecon_kernel, cudaFuncAttributeMaxDynamicSharedMemorySize, 65536);
    cudaFuncSetAttribute(mlp_kernel,     cudaFuncAttributeMaxDynamicSharedMemorySize, 131072);
    cudaFuncSetAttribute(fc_kernel,      cudaFuncAttributeMaxDynamicSharedMemorySize, 65536);

    dim3 gtile(Nn/128, 1, Bb);
    dim3 gproj(Nn/PROJ_NT, 1, Bb);

    bases_kernel<<<(Bb*Nn*Kk + 255)/256, 256>>>(nodes, modes, node_mask, node_weights);
    fc0_kernel<<<(Bb*Cc*Nn + 255)/256, 256>>>(x, fc0_w, fc0_b);

    for (int l = 0; l < 4; l++){
        zero_spec_kernel<<<64, 256>>>();
        proj2_kernel<<<gproj, 256>>>();
        specmix_kernel<<<64, 256>>>(sp_wc + (size_t)l*Cc*Cc*Kk,
                                    sp_ws + (size_t)l*Cc*Cc*Kk);
        specmix0_kernel<<<1, 256>>>(sp_w0 + (size_t)l*Cc*Cc);
        pwrecon_kernel<<<gtile, 256, 65536>>>(w_w + (size_t)l*Cc*Cc,
                                              w_b + (size_t)l*Cc, node_mask);
        if (l < 3){
            mlp_kernel<<<gtile, 256, 131072>>>(gw1 + (size_t)l*Cc*Cc, gb1 + (size_t)l*Cc,
                                               gw2 + (size_t)l*Cc*Cc, gb2 + (size_t)l*Cc);
            zero_x3_kernel<<<(Bb*Cc*Nn + 255)/256, 256>>>();
            ker_kernel<<<(Bb*Ee + 255)/256, 256>>>(edges, nodes,
                                                   isigma_w + l*4, isigma_b + l*2, gC, l);
            scatter_kernel<<<(Bb*Ee)/8, 256>>>(edges);
            combine_kernel<<<(Bb*Cc*Nn + 255)/256, 256>>>();
        }
    }
    fc_kernel<<<gtile, 256, 65536>>>(fc1_w, fc1_b, fc2_w, fc2_b, out);
}